// round 2
// baseline (speedup 1.0000x reference)
#include <cuda_runtime.h>
#include <cuda.h>
#include <cuda_bf16.h>
#include <cstdint>

// ---------------- problem constants ----------------
#define MROWS 4096           // 8*512 batch rows
#define NOUT  4096           // OUTF
#define KSEG  4096           // INF
#define KTOT  12288          // 3 segments: x_hi|x_lo|x_hi  vs  W_hi;W_hi;W_lo

// ---------------- GEMM tiling ----------------
#define TILE_M 128
#define TILE_N 256
#define TILE_K 64            // 64 bf16 = 128 bytes = one SW128 row
#define STAGES 4
#define KITERS (KTOT / TILE_K)   // 192

#define A_TILE_BYTES (TILE_M * 128)   // 16384
#define B_TILE_BYTES (TILE_N * 128)   // 32768
#define STAGE_BYTES  (A_TILE_BYTES + B_TILE_BYTES)
#define SMEM_TILES_OFF 1024
#define SMEM_TOTAL   (SMEM_TILES_OFF + STAGES * STAGE_BYTES)  // 197632

// idesc kind::f16: dtype=F32(bit4), atype=BF16(bit7), btype=BF16(bit10),
// N/8 << 17, M/16 << 24
#define MMA_IDESC (0x490u | ((TILE_N / 8) << 17) | ((TILE_M / 16) << 24))

// ---------------- scratch (device globals: no allocation allowed) ----------------
__device__ __align__(1024) __nv_bfloat16 g_A[(size_t)MROWS * KTOT];  // 96 MB
__device__ __align__(1024) __nv_bfloat16 g_B[(size_t)NOUT * KTOT];   // 96 MB

// ---------------- PTX helpers ----------------
__device__ __forceinline__ uint32_t smem_to_u32(const void* p) {
    uint32_t a;
    asm("{ .reg .u64 t; cvta.to.shared.u64 t, %1; cvt.u32.u64 %0, t; }" : "=r"(a) : "l"(p));
    return a;
}

#define MBARRIER_INIT(addr, cnt) \
    asm volatile("mbarrier.init.shared.b64 [%0], %1;" :: "r"((uint32_t)(addr)), "r"((uint32_t)(cnt)) : "memory")

#define MBARRIER_EXPECT_TX(addr, bytes) \
    asm volatile("mbarrier.arrive.expect_tx.shared.b64 _, [%0], %1;" :: "r"((uint32_t)(addr)), "r"((uint32_t)(bytes)) : "memory")

#define MBARRIER_WAIT_PARITY(addr, parity) do { \
    uint32_t _m = (uint32_t)(addr); uint32_t _p = (uint32_t)(parity); uint32_t _d; \
    asm volatile("{\n\t.reg .pred p;\n\t" \
        "mbarrier.try_wait.parity.acquire.cta.shared::cta.b64 p, [%1], %2;\n\t" \
        "selp.b32 %0, 1, 0, p;\n\t}" : "=r"(_d) : "r"(_m), "r"(_p) : "memory"); \
    if (!_d) { \
        asm volatile("{\n\t.reg .pred P1;\n\t" \
            "WL_%=:\n\t" \
            "mbarrier.try_wait.parity.acquire.cta.shared::cta.b64 P1, [%0], %1, 0x989680;\n\t" \
            "@P1 bra.uni WD_%=;\n\t" \
            "bra.uni WL_%=;\n\t" \
            "WD_%=:\n\t}" :: "r"(_m), "r"(_p) : "memory"); \
    } \
} while (0)

#define FENCE_PROXY_ASYNC() asm volatile("fence.proxy.async.shared::cta;" ::: "memory")

// -------- tcgen05 (sm_103a-only; must stay inside __CUDA_ARCH_FEAT_SM103_ALL) --------
#define TCGEN05_ALLOC(smem_addr, ncols) \
    asm volatile("tcgen05.alloc.cta_group::1.sync.aligned.shared::cta.b32 [%0], %1;" \
        :: "r"((uint32_t)(smem_addr)), "r"((uint32_t)(ncols)) : "memory")

#define TCGEN05_DEALLOC(tmem, ncols) \
    asm volatile("tcgen05.dealloc.cta_group::1.sync.aligned.b32 %0, %1;" :: "r"(tmem), "r"((uint32_t)(ncols)))

#define TCGEN05_RELINQUISH() \
    asm volatile("tcgen05.relinquish_alloc_permit.cta_group::1.sync.aligned;")

#define TCGEN05_COMMIT(mbar) \
    asm volatile("tcgen05.commit.cta_group::1.mbarrier::arrive::one.shared::cluster.b64 [%0];" \
        :: "r"((uint32_t)(mbar)) : "memory")

#define TCGEN05_FENCE_AFTER()  asm volatile("tcgen05.fence::after_thread_sync;" ::: "memory")
#define TCGEN05_FENCE_BEFORE() asm volatile("tcgen05.fence::before_thread_sync;" ::: "memory")
#define TCGEN05_WAIT_LD()      asm volatile("tcgen05.wait::ld.sync.aligned;" ::: "memory")

#define TCGEN05_LD_32X32B_X32(r, tmem_addr) \
    asm volatile( \
        "tcgen05.ld.sync.aligned.32x32b.x32.b32 " \
        "{%0, %1, %2, %3, %4, %5, %6, %7, " \
        " %8, %9, %10, %11, %12, %13, %14, %15, " \
        " %16, %17, %18, %19, %20, %21, %22, %23, " \
        " %24, %25, %26, %27, %28, %29, %30, %31}, [%32];" \
        : "=r"((r)[0]),  "=r"((r)[1]),  "=r"((r)[2]),  "=r"((r)[3]), \
          "=r"((r)[4]),  "=r"((r)[5]),  "=r"((r)[6]),  "=r"((r)[7]), \
          "=r"((r)[8]),  "=r"((r)[9]),  "=r"((r)[10]), "=r"((r)[11]), \
          "=r"((r)[12]), "=r"((r)[13]), "=r"((r)[14]), "=r"((r)[15]), \
          "=r"((r)[16]), "=r"((r)[17]), "=r"((r)[18]), "=r"((r)[19]), \
          "=r"((r)[20]), "=r"((r)[21]), "=r"((r)[22]), "=r"((r)[23]), \
          "=r"((r)[24]), "=r"((r)[25]), "=r"((r)[26]), "=r"((r)[27]), \
          "=r"((r)[28]), "=r"((r)[29]), "=r"((r)[30]), "=r"((r)[31]) \
        : "r"(tmem_addr))

// SW128 K-major SMEM descriptor: layout=2, version=1, SBO=64, LBO=1
static constexpr uint64_t SMEM_DESC_BASE_SW128 =
    (uint64_t(2) << 61) | (uint64_t(1) << 46) | (uint64_t(64) << 32) | (uint64_t(1) << 16);
#define MAKE_SMEM_DESC(base_addr) (SMEM_DESC_BASE_SW128 | ((uint64_t)((base_addr) >> 4) & 0x3FFF))

__device__ __forceinline__ void tma_load_2d(uint32_t smem_addr, const void* tmap,
                                            int32_t cx, int32_t cy, uint32_t mbar) {
    asm volatile(
        "cp.async.bulk.tensor.2d.shared::cta.global.tile.mbarrier::complete_tx::bytes "
        "[%0], [%1, {%2, %3}], [%4];"
        :: "r"(smem_addr), "l"(tmap), "r"(cx), "r"(cy), "r"(mbar) : "memory");
}

#if defined(__CUDA_ARCH__) && defined(__CUDA_ARCH_FEAT_SM103_ALL)
__device__ __forceinline__ void mma_f16_ss(uint32_t d_tmem, uint64_t a_desc, uint64_t b_desc,
                                           uint32_t idesc, bool acc) {
    uint32_t en = acc ? 1u : 0u;
    asm volatile(
        "{\n\t.reg .pred p;\n\tsetp.ne.u32 p, %4, 0;\n\t"
        "tcgen05.mma.cta_group::1.kind::f16 [%0], %1, %2, %3, {%5, %5, %5, %5}, p;\n\t}"
        :: "r"(d_tmem), "l"(a_desc), "l"(b_desc), "r"(idesc), "r"(en), "r"(0u) : "memory");
}
#endif

// ---------------- prologue 1: split x (fp32 -> bf16 hi/lo), build A' ----------------
__global__ void __launch_bounds__(256) split_x_kernel(const float* __restrict__ x) {
    size_t i = (size_t)blockIdx.x * blockDim.x + threadIdx.x;   // one float4 each
    float4 v = reinterpret_cast<const float4*>(x)[i];
    size_t row = i >> 10;            // 1024 float4 per row of 4096
    size_t col = (i & 1023) << 2;
    float f[4] = {v.x, v.y, v.z, v.w};
    __nv_bfloat16 h[4], l[4];
#pragma unroll
    for (int j = 0; j < 4; j++) {
        h[j] = __float2bfloat16(f[j]);
        l[j] = __float2bfloat16(f[j] - __bfloat162float(h[j]));
    }
    __nv_bfloat16* base = g_A + row * KTOT + col;
    *reinterpret_cast<uint2*>(base)            = *reinterpret_cast<uint2*>(h);  // seg0: x_hi
    *reinterpret_cast<uint2*>(base + KSEG)     = *reinterpret_cast<uint2*>(l);  // seg1: x_lo
    *reinterpret_cast<uint2*>(base + 2 * KSEG) = *reinterpret_cast<uint2*>(h);  // seg2: x_hi
}

// ---------------- prologue 2: dequant + transpose, build B' (N-major, K contiguous) ----------------
__global__ void __launch_bounds__(256) dequant_kernel(const int* __restrict__ qw,
                                                      const int* __restrict__ qz,
                                                      const float* __restrict__ sc) {
    int i = blockIdx.x * blockDim.x + threadIdx.x;  // 512 * 4096 threads
    int n  = i & (NOUT - 1);
    int kp = i >> 12;                 // packed-k row index [0, 512)
    int g  = kp >> 4;                 // group = kp*8/128
    unsigned w  = (unsigned)qw[(size_t)kp * NOUT + n];
    unsigned zw = (unsigned)qz[(size_t)g * (NOUT / 8) + (n >> 3)];
    float z = (float)(((zw >> ((n & 7) * 4)) & 15u) + 1u);
    float s = sc[(size_t)g * NOUT + n];
    __nv_bfloat16 h[8], l[8];
#pragma unroll
    for (int j = 0; j < 8; j++) {
        float wv = (float)((w >> (4 * j)) & 15u);
        float W = s * (wv - z);
        h[j] = __float2bfloat16(W);
        l[j] = __float2bfloat16(W - __bfloat162float(h[j]));
    }
    __nv_bfloat16* base = g_B + (size_t)n * KTOT + (size_t)kp * 8;
    *reinterpret_cast<uint4*>(base)            = *reinterpret_cast<uint4*>(h);  // seg0: W_hi
    *reinterpret_cast<uint4*>(base + KSEG)     = *reinterpret_cast<uint4*>(h);  // seg1: W_hi
    *reinterpret_cast<uint4*>(base + 2 * KSEG) = *reinterpret_cast<uint4*>(l);  // seg2: W_lo
}

// ---------------- GEMM: warp-specialized tcgen05, 4-stage TMA pipeline ----------------
// warps 0-3: epilogue (TMEM -> GMEM), warp 4: TMA producer, warp 5: MMA
// Body exists only in the sm_103a (feature) compilation pass.
__global__ void __launch_bounds__(192, 1) gemm_kernel(
    const __grid_constant__ CUtensorMap tmapA,
    const __grid_constant__ CUtensorMap tmapB,
    const float* __restrict__ bias,
    float* __restrict__ out)
{
#if defined(__CUDA_ARCH__) && defined(__CUDA_ARCH_FEAT_SM103_ALL)
    extern __shared__ __align__(1024) char smem[];
    uint32_t sb = smem_to_u32(smem);
    const int tid = threadIdx.x, wid = tid >> 5, lid = tid & 31;
    const int ntile = blockIdx.x, mtile = blockIdx.y;

    const uint32_t tmem_ptr_addr = sb + 0;
    auto full_bar  = [&](int s) { return sb + 64 + s * 8; };
    auto empty_bar = [&](int s) { return sb + 96 + s * 8; };
    const uint32_t done_bar = sb + 128;
    auto stageA = [&](int s) { return sb + SMEM_TILES_OFF + s * STAGE_BYTES; };
    auto stageB = [&](int s) { return sb + SMEM_TILES_OFF + s * STAGE_BYTES + A_TILE_BYTES; };

    if (tid == 0) {
#pragma unroll
        for (int s = 0; s < STAGES; s++) {
            MBARRIER_INIT(full_bar(s), 1);
            MBARRIER_INIT(empty_bar(s), 1);
        }
        MBARRIER_INIT(done_bar, 1);
        FENCE_PROXY_ASYNC();
    }
    if (wid == 5) {  // warp-collective TMEM alloc
        TCGEN05_ALLOC(tmem_ptr_addr, 256);
        TCGEN05_RELINQUISH();
    }
    __syncthreads();

    uint32_t tmem_base;
    asm volatile("ld.shared.b32 %0, [%1];" : "=r"(tmem_base) : "r"(tmem_ptr_addr));

    if (wid == 4 && lid == 0) {
        // ---- TMA producer ----
        int s = 0, ph = 1;
        for (int it = 0; it < KITERS; it++) {
            MBARRIER_WAIT_PARITY(empty_bar(s), ph);
            MBARRIER_EXPECT_TX(full_bar(s), STAGE_BYTES);
            tma_load_2d(stageA(s), &tmapA, it * TILE_K, mtile * TILE_M, full_bar(s));
            tma_load_2d(stageB(s), &tmapB, it * TILE_K, ntile * TILE_N, full_bar(s));
            if (++s == STAGES) { s = 0; ph ^= 1; }
        }
    } else if (wid == 5 && lid == 0) {
        // ---- MMA issuer ----
        int s = 0, ph = 0;
        for (int it = 0; it < KITERS; it++) {
            MBARRIER_WAIT_PARITY(full_bar(s), ph);
            uint64_t ad = MAKE_SMEM_DESC(stageA(s));
            uint64_t bd = MAKE_SMEM_DESC(stageB(s));
#pragma unroll
            for (int k = 0; k < 4; k++)  // 4 x K=16 per 64-K tile; +2 = +32B desc step
                mma_f16_ss(tmem_base, ad + k * 2, bd + k * 2, MMA_IDESC, !(it == 0 && k == 0));
            TCGEN05_COMMIT(empty_bar(s));   // arrives when all issued MMAs are done
            if (++s == STAGES) { s = 0; ph ^= 1; }
        }
        TCGEN05_COMMIT(done_bar);
    } else if (wid < 4) {
        // ---- epilogue ----
        MBARRIER_WAIT_PARITY(done_bar, 0);
        TCGEN05_FENCE_AFTER();
        const int m = mtile * TILE_M + wid * 32 + lid;
        float* orow = out + (size_t)m * NOUT + ntile * TILE_N;
#pragma unroll
        for (int cb = 0; cb < TILE_N / 32; cb++) {
            uint32_t r[32];
            TCGEN05_LD_32X32B_X32(r, tmem_base + cb * 32);
            TCGEN05_WAIT_LD();
            const int n0 = ntile * TILE_N + cb * 32;
#pragma unroll
            for (int i = 0; i < 32; i += 4) {
                float4 b4 = *reinterpret_cast<const float4*>(bias + n0 + i);
                float4 v;
                v.x = __uint_as_float(r[i + 0]) + b4.x;
                v.y = __uint_as_float(r[i + 1]) + b4.y;
                v.z = __uint_as_float(r[i + 2]) + b4.z;
                v.w = __uint_as_float(r[i + 3]) + b4.w;
                *reinterpret_cast<float4*>(orow + cb * 32 + i) = v;
            }
        }
        TCGEN05_FENCE_BEFORE();
    }

    __syncthreads();
    if (wid == 5) TCGEN05_DEALLOC(tmem_base, 256);
#endif  // __CUDA_ARCH_FEAT_SM103_ALL
}

// ---------------- fallback GEMM (body only when tcgen05 is unavailable) ----------------
// Plain smem-tiled fp32-FMA GEMM on the same g_A/g_B split operands. Correct but slow;
// runs only if the loaded cubin is the non-'a' sm_103 variant. Otherwise this kernel
// compiles to an empty shell and its launch is a no-op.
#define FB_TM 128
#define FB_TN 128
#define FB_TK 32

__global__ void __launch_bounds__(256) gemm_fallback(const float* __restrict__ bias,
                                                     float* __restrict__ out) {
#if defined(__CUDA_ARCH__) && !defined(__CUDA_ARCH_FEAT_SM103_ALL)
    __shared__ __nv_bfloat16 sA[FB_TK][FB_TM + 4];
    __shared__ __nv_bfloat16 sB[FB_TK][FB_TN + 4];
    const int tid = threadIdx.x;
    const int m0 = blockIdx.y * FB_TM, n0 = blockIdx.x * FB_TN;
    const int tm = (tid >> 4) * 8, tn = (tid & 15) * 8;
    float acc[8][8] = {};
    for (int k0 = 0; k0 < KTOT; k0 += FB_TK) {
        __syncthreads();
        for (int idx = tid; idx < FB_TM * FB_TK / 8; idx += 256) {
            int row = idx >> 2;          // 4 uint4-chunks per row (32 k)
            int kc  = (idx & 3) * 8;
            __nv_bfloat16 ta[8], tb[8];
            *reinterpret_cast<uint4*>(ta) =
                *reinterpret_cast<const uint4*>(&g_A[(size_t)(m0 + row) * KTOT + k0 + kc]);
            *reinterpret_cast<uint4*>(tb) =
                *reinterpret_cast<const uint4*>(&g_B[(size_t)(n0 + row) * KTOT + k0 + kc]);
#pragma unroll
            for (int j = 0; j < 8; j++) { sA[kc + j][row] = ta[j]; sB[kc + j][row] = tb[j]; }
        }
        __syncthreads();
#pragma unroll 4
        for (int kk = 0; kk < FB_TK; kk++) {
            float a[8], b[8];
#pragma unroll
            for (int j = 0; j < 8; j++) a[j] = __bfloat162float(sA[kk][tm + j]);
#pragma unroll
            for (int j = 0; j < 8; j++) b[j] = __bfloat162float(sB[kk][tn + j]);
#pragma unroll
            for (int i = 0; i < 8; i++)
#pragma unroll
                for (int j = 0; j < 8; j++) acc[i][j] += a[i] * b[j];
        }
    }
#pragma unroll
    for (int i = 0; i < 8; i++)
#pragma unroll
        for (int j = 0; j < 8; j++)
            out[(size_t)(m0 + tm + i) * NOUT + n0 + tn + j] = acc[i][j] + bias[n0 + tn + j];
#endif
}

// ---------------- host ----------------
typedef CUresult (*PFN_encodeTiled)(CUtensorMap*, CUtensorMapDataType, cuuint32_t, void*,
                                    const cuuint64_t*, const cuuint64_t*, const cuuint32_t*,
                                    const cuuint32_t*, CUtensorMapInterleave, CUtensorMapSwizzle,
                                    CUtensorMapL2promotion, CUtensorMapFloatOOBfill);

static void make_tmap(PFN_encodeTiled enc, CUtensorMap* m, void* ptr,
                      uint64_t rows, uint32_t box_rows) {
    cuuint64_t dims[2]    = {(cuuint64_t)KTOT, (cuuint64_t)rows};
    cuuint64_t strides[1] = {(cuuint64_t)KTOT * 2};
    cuuint32_t box[2]     = {(cuuint32_t)TILE_K, (cuuint32_t)box_rows};  // 64 bf16 = 128 B
    cuuint32_t es[2]      = {1, 1};
    enc(m, CU_TENSOR_MAP_DATA_TYPE_BFLOAT16, 2, ptr, dims, strides, box, es,
        CU_TENSOR_MAP_INTERLEAVE_NONE, CU_TENSOR_MAP_SWIZZLE_128B,
        CU_TENSOR_MAP_L2_PROMOTION_L2_128B, CU_TENSOR_MAP_FLOAT_OOB_FILL_NONE);
}

extern "C" void kernel_launch(void* const* d_in, const int* in_sizes, int n_in,
                              void* d_out, int out_size) {
    const float* x    = (const float*)d_in[0];
    const int*   qw   = (const int*)d_in[1];
    const int*   qz   = (const int*)d_in[2];
    const float* sc   = (const float*)d_in[3];
    const float* bias = (const float*)d_in[4];
    float* out        = (float*)d_out;

    void* pA = nullptr; void* pB = nullptr;
    cudaGetSymbolAddress(&pA, g_A);
    cudaGetSymbolAddress(&pB, g_B);

    void* fn = nullptr;
    cudaDriverEntryPointQueryResult qr;
    cudaGetDriverEntryPointByVersion("cuTensorMapEncodeTiled", &fn, 12000,
                                     cudaEnableDefault, &qr);
    PFN_encodeTiled enc = (PFN_encodeTiled)fn;

    CUtensorMap tA, tB;
    make_tmap(enc, &tA, pA, MROWS, TILE_M);
    make_tmap(enc, &tB, pB, NOUT, TILE_N);

    cudaFuncSetAttribute(gemm_kernel, cudaFuncAttributeMaxDynamicSharedMemorySize, SMEM_TOTAL);

    // prologues
    split_x_kernel<<<(MROWS * KSEG / 4) / 256, 256>>>(x);          // 16384 blocks
    dequant_kernel<<<(512 * NOUT) / 256, 256>>>(qw, qz, sc);       // 8192 blocks

    // GEMM: 16 N-tiles x 32 M-tiles (real work in exactly one of these two,
    // depending on which arch variant the runtime loaded; the other is empty)
    gemm_kernel<<<dim3(NOUT / TILE_N, MROWS / TILE_M), 192, SMEM_TOTAL>>>(tA, tB, bias, out);
    gemm_fallback<<<dim3(NOUT / FB_TN, MROWS / FB_TM), 256>>>(bias, out);
}

// round 3
// speedup vs baseline: 2.5883x; 2.5883x over previous
#include <cuda_runtime.h>
#include <cuda.h>
#include <cuda_bf16.h>
#include <cuda_fp16.h>
#include <cstdint>

// ---------------- problem constants ----------------
#define MROWS 4096           // 8*512 batch rows
#define NOUT  4096           // OUTF
#define KSEG  4096           // INF == GEMM K (single fp16 pass)

// ---------------- GEMM tiling ----------------
#define TILE_M 128
#define TILE_N 256
#define TILE_K 64            // 64 fp16 = 128 bytes = one SW128 row
#define STAGES 4
#define KITERS (KSEG / TILE_K)   // 64

#define A_TILE_BYTES (TILE_M * 128)   // 16384
#define B_TILE_BYTES (TILE_N * 128)   // 32768
#define A_SLICE_BYTES (A_TILE_BYTES / 2)   // 8192  (64 rows)
#define B_SLICE_BYTES (B_TILE_BYTES / 2)   // 16384 (128 rows)
#define STAGE_BYTES  (A_TILE_BYTES + B_TILE_BYTES)
#define SMEM_TILES_OFF 1024
#define SMEM_TOTAL   (SMEM_TILES_OFF + STAGES * STAGE_BYTES)  // 197632

// idesc kind::f16 fp16 inputs: dtype=F32(bit4), atype=F16(0), btype=F16(0),
// N/8 << 17, M/16 << 24
#define MMA_IDESC (0x10u | ((TILE_N / 8) << 17) | ((TILE_M / 16) << 24))

// ---------------- scratch (device globals: no allocation allowed) ----------------
__device__ __align__(1024) __half g_A[(size_t)MROWS * KSEG];  // 32 MB  (x in fp16)
__device__ __align__(1024) __half g_B[(size_t)NOUT * KSEG];   // 32 MB  (W^T in fp16)

// ---------------- PTX helpers ----------------
__device__ __forceinline__ uint32_t smem_to_u32(const void* p) {
    uint32_t a;
    asm("{ .reg .u64 t; cvta.to.shared.u64 t, %1; cvt.u32.u64 %0, t; }" : "=r"(a) : "l"(p));
    return a;
}

#define MBARRIER_INIT(addr, cnt) \
    asm volatile("mbarrier.init.shared.b64 [%0], %1;" :: "r"((uint32_t)(addr)), "r"((uint32_t)(cnt)) : "memory")

#define MBARRIER_EXPECT_TX(addr, bytes) \
    asm volatile("mbarrier.arrive.expect_tx.shared.b64 _, [%0], %1;" :: "r"((uint32_t)(addr)), "r"((uint32_t)(bytes)) : "memory")

#define MBARRIER_WAIT_PARITY(addr, parity) do { \
    uint32_t _m = (uint32_t)(addr); uint32_t _p = (uint32_t)(parity); uint32_t _d; \
    asm volatile("{\n\t.reg .pred p;\n\t" \
        "mbarrier.try_wait.parity.acquire.cta.shared::cta.b64 p, [%1], %2;\n\t" \
        "selp.b32 %0, 1, 0, p;\n\t}" : "=r"(_d) : "r"(_m), "r"(_p) : "memory"); \
    if (!_d) { \
        asm volatile("{\n\t.reg .pred P1;\n\t" \
            "WL_%=:\n\t" \
            "mbarrier.try_wait.parity.acquire.cta.shared::cta.b64 P1, [%0], %1, 0x989680;\n\t" \
            "@P1 bra.uni WD_%=;\n\t" \
            "bra.uni WL_%=;\n\t" \
            "WD_%=:\n\t}" :: "r"(_m), "r"(_p) : "memory"); \
    } \
} while (0)

#define FENCE_PROXY_ASYNC() asm volatile("fence.proxy.async.shared::cta;" ::: "memory")

#define CLUSTER_SYNC() do { \
    asm volatile("barrier.cluster.arrive.aligned;" ::: "memory"); \
    asm volatile("barrier.cluster.wait.aligned;" ::: "memory"); \
} while (0)

// -------- tcgen05 (sm_103a-only; must stay inside __CUDA_ARCH_FEAT_SM103_ALL) --------
#define TCGEN05_ALLOC(smem_addr, ncols) \
    asm volatile("tcgen05.alloc.cta_group::1.sync.aligned.shared::cta.b32 [%0], %1;" \
        :: "r"((uint32_t)(smem_addr)), "r"((uint32_t)(ncols)) : "memory")

#define TCGEN05_DEALLOC(tmem, ncols) \
    asm volatile("tcgen05.dealloc.cta_group::1.sync.aligned.b32 %0, %1;" :: "r"(tmem), "r"((uint32_t)(ncols)))

#define TCGEN05_RELINQUISH() \
    asm volatile("tcgen05.relinquish_alloc_permit.cta_group::1.sync.aligned;")

#define TCGEN05_COMMIT(mbar) \
    asm volatile("tcgen05.commit.cta_group::1.mbarrier::arrive::one.shared::cluster.b64 [%0];" \
        :: "r"((uint32_t)(mbar)) : "memory")

#define TCGEN05_COMMIT_MULTICAST(mbar, mask) \
    asm volatile("tcgen05.commit.cta_group::1.mbarrier::arrive::one.shared::cluster.multicast::cluster.b64 [%0], %1;" \
        :: "r"((uint32_t)(mbar)), "h"((uint16_t)(mask)) : "memory")

#define TCGEN05_FENCE_AFTER()  asm volatile("tcgen05.fence::after_thread_sync;" ::: "memory")
#define TCGEN05_FENCE_BEFORE() asm volatile("tcgen05.fence::before_thread_sync;" ::: "memory")
#define TCGEN05_WAIT_LD()      asm volatile("tcgen05.wait::ld.sync.aligned;" ::: "memory")

#define TCGEN05_LD_32X32B_X32(r, tmem_addr) \
    asm volatile( \
        "tcgen05.ld.sync.aligned.32x32b.x32.b32 " \
        "{%0, %1, %2, %3, %4, %5, %6, %7, " \
        " %8, %9, %10, %11, %12, %13, %14, %15, " \
        " %16, %17, %18, %19, %20, %21, %22, %23, " \
        " %24, %25, %26, %27, %28, %29, %30, %31}, [%32];" \
        : "=r"((r)[0]),  "=r"((r)[1]),  "=r"((r)[2]),  "=r"((r)[3]), \
          "=r"((r)[4]),  "=r"((r)[5]),  "=r"((r)[6]),  "=r"((r)[7]), \
          "=r"((r)[8]),  "=r"((r)[9]),  "=r"((r)[10]), "=r"((r)[11]), \
          "=r"((r)[12]), "=r"((r)[13]), "=r"((r)[14]), "=r"((r)[15]), \
          "=r"((r)[16]), "=r"((r)[17]), "=r"((r)[18]), "=r"((r)[19]), \
          "=r"((r)[20]), "=r"((r)[21]), "=r"((r)[22]), "=r"((r)[23]), \
          "=r"((r)[24]), "=r"((r)[25]), "=r"((r)[26]), "=r"((r)[27]), \
          "=r"((r)[28]), "=r"((r)[29]), "=r"((r)[30]), "=r"((r)[31]) \
        : "r"(tmem_addr))

// SW128 K-major SMEM descriptor: layout=2, version=1, SBO=64, LBO=1
static constexpr uint64_t SMEM_DESC_BASE_SW128 =
    (uint64_t(2) << 61) | (uint64_t(1) << 46) | (uint64_t(64) << 32) | (uint64_t(1) << 16);
#define MAKE_SMEM_DESC(base_addr) (SMEM_DESC_BASE_SW128 | ((uint64_t)((base_addr) >> 4) & 0x3FFF))

__device__ __forceinline__ void tma_load_2d_mc(uint32_t smem_addr, const void* tmap,
                                               int32_t cx, int32_t cy, uint32_t mbar,
                                               uint16_t mask) {
    asm volatile(
        "cp.async.bulk.tensor.2d.shared::cluster.global.tile.mbarrier::complete_tx::bytes.multicast::cluster "
        "[%0], [%1, {%2, %3}], [%4], %5;"
        :: "r"(smem_addr), "l"(tmap), "r"(cx), "r"(cy), "r"(mbar), "h"(mask) : "memory");
}

#if defined(__CUDA_ARCH__) && defined(__CUDA_ARCH_FEAT_SM103_ALL)
__device__ __forceinline__ void mma_f16_ss(uint32_t d_tmem, uint64_t a_desc, uint64_t b_desc,
                                           uint32_t idesc, bool acc) {
    uint32_t en = acc ? 1u : 0u;
    asm volatile(
        "{\n\t.reg .pred p;\n\tsetp.ne.u32 p, %4, 0;\n\t"
        "tcgen05.mma.cta_group::1.kind::f16 [%0], %1, %2, %3, {%5, %5, %5, %5}, p;\n\t}"
        :: "r"(d_tmem), "l"(a_desc), "l"(b_desc), "r"(idesc), "r"(en), "r"(0u) : "memory");
}
#endif

// ---------------- prologue 1: x fp32 -> fp16 ----------------
__global__ void __launch_bounds__(256) cvt_x_kernel(const float* __restrict__ x) {
    size_t i = (size_t)blockIdx.x * blockDim.x + threadIdx.x;   // one float4 each
    float4 v = reinterpret_cast<const float4*>(x)[i];
    __half h[4];
    h[0] = __float2half_rn(v.x);
    h[1] = __float2half_rn(v.y);
    h[2] = __float2half_rn(v.z);
    h[3] = __float2half_rn(v.w);
    *reinterpret_cast<uint2*>(g_A + i * 4) = *reinterpret_cast<uint2*>(h);
}

// ---------------- prologue 2: dequant + transpose -> W^T fp16 (N-major, K contiguous) -------
__global__ void __launch_bounds__(256) dequant_kernel(const int* __restrict__ qw,
                                                      const int* __restrict__ qz,
                                                      const float* __restrict__ sc) {
    int i = blockIdx.x * blockDim.x + threadIdx.x;  // 512 * 4096 threads
    int n  = i & (NOUT - 1);
    int kp = i >> 12;                 // packed-k row index [0, 512)
    int g  = kp >> 4;                 // group = kp*8/128
    unsigned w  = (unsigned)qw[(size_t)kp * NOUT + n];
    unsigned zw = (unsigned)qz[(size_t)g * (NOUT / 8) + (n >> 3)];
    float z = (float)(((zw >> ((n & 7) * 4)) & 15u) + 1u);
    float s = sc[(size_t)g * NOUT + n];
    __half h[8];
#pragma unroll
    for (int j = 0; j < 8; j++) {
        float wv = (float)((w >> (4 * j)) & 15u);
        h[j] = __float2half_rn(s * (wv - z));
    }
    *reinterpret_cast<uint4*>(g_B + (size_t)n * KSEG + (size_t)kp * 8) =
        *reinterpret_cast<uint4*>(h);
}

// ---------------- GEMM: warp-specialized tcgen05, 4-stage TMA pipeline, 2x2 cluster -------
// warps 0-3: epilogue (TMEM -> GMEM), warp 4: TMA producer, warp 5: MMA
// Cluster (2,2,1): A tile multicast across x-pairs (same mtile, cooperative 64-row
// slices), B tile multicast across y-pairs (same ntile, cooperative 128-row slices).
__global__ void __launch_bounds__(192, 1) __cluster_dims__(2, 2, 1) gemm_kernel(
    const __grid_constant__ CUtensorMap tmapA,
    const __grid_constant__ CUtensorMap tmapB,
    const float* __restrict__ bias,
    float* __restrict__ out)
{
#if defined(__CUDA_ARCH__) && defined(__CUDA_ARCH_FEAT_SM103_ALL)
    extern __shared__ __align__(1024) char smem[];
    uint32_t sb = smem_to_u32(smem);
    const int tid = threadIdx.x, wid = tid >> 5, lid = tid & 31;
    const int ntile = blockIdx.x, mtile = blockIdx.y;
    const int cx = blockIdx.x & 1, cy = blockIdx.y & 1;
    // rank = cy*2 + cx. A partners: same cy -> mask 0b11<<(2cy).
    // B partners: same cx -> mask 0b0101<<cx. All: 0b1111.
    const uint16_t maskA = (uint16_t)(0x3u << (2 * cy));
    const uint16_t maskB = (uint16_t)(0x5u << cx);

    const uint32_t tmem_ptr_addr = sb + 0;
    auto full_bar  = [&](int s) { return sb + 64 + s * 8; };
    auto empty_bar = [&](int s) { return sb + 128 + s * 8; };
    const uint32_t done_bar = sb + 192;
    auto stageA = [&](int s) { return sb + SMEM_TILES_OFF + s * STAGE_BYTES; };
    auto stageB = [&](int s) { return sb + SMEM_TILES_OFF + s * STAGE_BYTES + A_TILE_BYTES; };

    if (tid == 0) {
#pragma unroll
        for (int s = 0; s < STAGES; s++) {
            MBARRIER_INIT(full_bar(s), 1);
            MBARRIER_INIT(empty_bar(s), 4);   // commit-multicast from all 4 cluster CTAs
        }
        MBARRIER_INIT(done_bar, 1);
        FENCE_PROXY_ASYNC();
    }
    if (wid == 5) {  // warp-collective TMEM alloc
        TCGEN05_ALLOC(tmem_ptr_addr, 256);
        TCGEN05_RELINQUISH();
    }
    __syncthreads();
    CLUSTER_SYNC();   // all mbarriers visible before any multicast TMA / commit

    uint32_t tmem_base;
    asm volatile("ld.shared.b32 %0, [%1];" : "=r"(tmem_base) : "r"(tmem_ptr_addr));

    if (wid == 4 && lid == 0) {
        // ---- TMA producer: cooperative slices, multicast to partners ----
        int s = 0, ph = 1;
        for (int it = 0; it < KITERS; it++) {
            MBARRIER_WAIT_PARITY(empty_bar(s), ph);
            MBARRIER_EXPECT_TX(full_bar(s), STAGE_BYTES);   // A(16K) + B(32K) arrive via 4 slices
            // A slice: 64 rows starting at mtile*128 + cx*64 -> both x-partners
            tma_load_2d_mc(stageA(s) + cx * A_SLICE_BYTES, &tmapA,
                           it * TILE_K, mtile * TILE_M + cx * 64, full_bar(s), maskA);
            // B slice: 128 rows starting at ntile*256 + cy*128 -> both y-partners
            tma_load_2d_mc(stageB(s) + cy * B_SLICE_BYTES, &tmapB,
                           it * TILE_K, ntile * TILE_N + cy * 128, full_bar(s), maskB);
            if (++s == STAGES) { s = 0; ph ^= 1; }
        }
    } else if (wid == 5 && lid == 0) {
        // ---- MMA issuer ----
        int s = 0, ph = 0;
        for (int it = 0; it < KITERS; it++) {
            MBARRIER_WAIT_PARITY(full_bar(s), ph);
            uint64_t ad = MAKE_SMEM_DESC(stageA(s));
            uint64_t bd = MAKE_SMEM_DESC(stageB(s));
#pragma unroll
            for (int k = 0; k < 4; k++)  // 4 x K=16 per 64-K tile; +2 = +32B desc step
                mma_f16_ss(tmem_base, ad + k * 2, bd + k * 2, MMA_IDESC, !(it == 0 && k == 0));
            TCGEN05_COMMIT_MULTICAST(empty_bar(s), 0xF);   // free this stage in all 4 CTAs
            if (++s == STAGES) { s = 0; ph ^= 1; }
        }
        TCGEN05_COMMIT(done_bar);
    } else if (wid < 4) {
        // ---- epilogue ----
        MBARRIER_WAIT_PARITY(done_bar, 0);
        TCGEN05_FENCE_AFTER();
        const int m = mtile * TILE_M + wid * 32 + lid;
        float* orow = out + (size_t)m * NOUT + ntile * TILE_N;
#pragma unroll
        for (int cb = 0; cb < TILE_N / 32; cb++) {
            uint32_t r[32];
            TCGEN05_LD_32X32B_X32(r, tmem_base + cb * 32);
            TCGEN05_WAIT_LD();
            const int n0 = ntile * TILE_N + cb * 32;
#pragma unroll
            for (int i = 0; i < 32; i += 4) {
                float4 b4 = *reinterpret_cast<const float4*>(bias + n0 + i);
                float4 v;
                v.x = __uint_as_float(r[i + 0]) + b4.x;
                v.y = __uint_as_float(r[i + 1]) + b4.y;
                v.z = __uint_as_float(r[i + 2]) + b4.z;
                v.w = __uint_as_float(r[i + 3]) + b4.w;
                *reinterpret_cast<float4*>(orow + cb * 32 + i) = v;
            }
        }
        TCGEN05_FENCE_BEFORE();
    }

    __syncthreads();
    if (wid == 5) TCGEN05_DEALLOC(tmem_base, 256);
    CLUSTER_SYNC();   // no CTA exits while peer multicast traffic may be in flight
#endif  // __CUDA_ARCH_FEAT_SM103_ALL
}

// ---------------- fallback GEMM (body only when tcgen05 is unavailable) ----------------
#define FB_TM 128
#define FB_TN 128
#define FB_TK 32

__global__ void __launch_bounds__(256) gemm_fallback(const float* __restrict__ bias,
                                                     float* __restrict__ out) {
#if defined(__CUDA_ARCH__) && !defined(__CUDA_ARCH_FEAT_SM103_ALL)
    __shared__ __half sA[FB_TK][FB_TM + 4];
    __shared__ __half sB[FB_TK][FB_TN + 4];
    const int tid = threadIdx.x;
    const int m0 = blockIdx.y * FB_TM, n0 = blockIdx.x * FB_TN;
    const int tm = (tid >> 4) * 8, tn = (tid & 15) * 8;
    float acc[8][8] = {};
    for (int k0 = 0; k0 < KSEG; k0 += FB_TK) {
        __syncthreads();
        for (int idx = tid; idx < FB_TM * FB_TK / 8; idx += 256) {
            int row = idx >> 2;
            int kc  = (idx & 3) * 8;
            __half ta[8], tb[8];
            *reinterpret_cast<uint4*>(ta) =
                *reinterpret_cast<const uint4*>(&g_A[(size_t)(m0 + row) * KSEG + k0 + kc]);
            *reinterpret_cast<uint4*>(tb) =
                *reinterpret_cast<const uint4*>(&g_B[(size_t)(n0 + row) * KSEG + k0 + kc]);
#pragma unroll
            for (int j = 0; j < 8; j++) { sA[kc + j][row] = ta[j]; sB[kc + j][row] = tb[j]; }
        }
        __syncthreads();
#pragma unroll 4
        for (int kk = 0; kk < FB_TK; kk++) {
            float a[8], b[8];
#pragma unroll
            for (int j = 0; j < 8; j++) a[j] = __half2float(sA[kk][tm + j]);
#pragma unroll
            for (int j = 0; j < 8; j++) b[j] = __half2float(sB[kk][tn + j]);
#pragma unroll
            for (int i = 0; i < 8; i++)
#pragma unroll
                for (int j = 0; j < 8; j++) acc[i][j] += a[i] * b[j];
        }
    }
#pragma unroll
    for (int i = 0; i < 8; i++)
#pragma unroll
        for (int j = 0; j < 8; j++)
            out[(size_t)(m0 + tm + i) * NOUT + n0 + tn + j] = acc[i][j] + bias[n0 + tn + j];
#endif
}

// ---------------- host ----------------
typedef CUresult (*PFN_encodeTiled)(CUtensorMap*, CUtensorMapDataType, cuuint32_t, void*,
                                    const cuuint64_t*, const cuuint64_t*, const cuuint32_t*,
                                    const cuuint32_t*, CUtensorMapInterleave, CUtensorMapSwizzle,
                                    CUtensorMapL2promotion, CUtensorMapFloatOOBfill);

static void make_tmap(PFN_encodeTiled enc, CUtensorMap* m, void* ptr,
                      uint64_t rows, uint32_t box_rows) {
    cuuint64_t dims[2]    = {(cuuint64_t)KSEG, (cuuint64_t)rows};
    cuuint64_t strides[1] = {(cuuint64_t)KSEG * 2};
    cuuint32_t box[2]     = {(cuuint32_t)TILE_K, (cuuint32_t)box_rows};  // 64 fp16 = 128 B
    cuuint32_t es[2]      = {1, 1};
    enc(m, CU_TENSOR_MAP_DATA_TYPE_FLOAT16, 2, ptr, dims, strides, box, es,
        CU_TENSOR_MAP_INTERLEAVE_NONE, CU_TENSOR_MAP_SWIZZLE_128B,
        CU_TENSOR_MAP_L2_PROMOTION_L2_128B, CU_TENSOR_MAP_FLOAT_OOB_FILL_NONE);
}

extern "C" void kernel_launch(void* const* d_in, const int* in_sizes, int n_in,
                              void* d_out, int out_size) {
    const float* x    = (const float*)d_in[0];
    const int*   qw   = (const int*)d_in[1];
    const int*   qz   = (const int*)d_in[2];
    const float* sc   = (const float*)d_in[3];
    const float* bias = (const float*)d_in[4];
    float* out        = (float*)d_out;

    void* pA = nullptr; void* pB = nullptr;
    cudaGetSymbolAddress(&pA, g_A);
    cudaGetSymbolAddress(&pB, g_B);

    void* fn = nullptr;
    cudaDriverEntryPointQueryResult qr;
    cudaGetDriverEntryPointByVersion("cuTensorMapEncodeTiled", &fn, 12000,
                                     cudaEnableDefault, &qr);
    PFN_encodeTiled enc = (PFN_encodeTiled)fn;

    CUtensorMap tA, tB;
    make_tmap(enc, &tA, pA, MROWS, 64);    // A loaded as 64-row cooperative slices
    make_tmap(enc, &tB, pB, NOUT, 128);    // B loaded as 128-row cooperative slices

    cudaFuncSetAttribute(gemm_kernel, cudaFuncAttributeMaxDynamicSharedMemorySize, SMEM_TOTAL);

    // prologues
    cvt_x_kernel<<<(MROWS * KSEG / 4) / 256, 256>>>(x);            // 16384 blocks
    dequant_kernel<<<(512 * NOUT) / 256, 256>>>(qw, qz, sc);       // 8192 blocks

    // GEMM: 16 N-tiles x 32 M-tiles, 2x2 clusters (real work in exactly one of
    // these two, depending on which arch variant loaded; the other is empty)
    gemm_kernel<<<dim3(NOUT / TILE_N, MROWS / TILE_M), 192, SMEM_TOTAL>>>(tA, tB, bias, out);
    gemm_fallback<<<dim3(NOUT / FB_TN, MROWS / FB_TM), 256>>>(bias, out);
}

// round 4
// speedup vs baseline: 3.0154x; 1.1650x over previous
#include <cuda_runtime.h>
#include <cuda.h>
#include <cuda_bf16.h>
#include <cuda_fp16.h>
#include <cstdint>

// ---------------- problem constants ----------------
#define MROWS 4096
#define NOUT  4096
#define KSEG  4096

// ---------------- GEMM tiling ----------------
#define TILE_M 128
#define TILE_N 256
#define TILE_K 64            // 64 fp16 = 128 bytes = one SW128 row
#define STAGES 4
#define KITERS (KSEG / TILE_K)   // 64

#define NCLUSTERS 33              // 33 clusters x 4 CTAs = 132 CTAs (persistent)
#define NSUPER    128             // (4096/256) * (4096/512) super-tiles
#define M_SUPERS  16              // 4096 / 256

#define A_TILE_BYTES (TILE_M * 128)   // 16384
#define B_TILE_BYTES (TILE_N * 128)   // 32768
#define A_SLICE_BYTES (A_TILE_BYTES / 2)   // 8192  (64 rows)
#define B_SLICE_BYTES (B_TILE_BYTES / 2)   // 16384 (128 rows)
#define STAGE_BYTES  (A_TILE_BYTES + B_TILE_BYTES)
#define SMEM_TILES_OFF 1024
#define SMEM_TOTAL   (SMEM_TILES_OFF + STAGES * STAGE_BYTES)  // 197632

// idesc kind::f16 fp16 inputs: dtype=F32(bit4), N/8 << 17, M/16 << 24
#define MMA_IDESC (0x10u | ((TILE_N / 8) << 17) | ((TILE_M / 16) << 24))

// ---------------- scratch ----------------
__device__ __align__(1024) __half g_A[(size_t)MROWS * KSEG];  // 32 MB
__device__ __align__(1024) __half g_B[(size_t)NOUT * KSEG];   // 32 MB

// ---------------- PTX helpers ----------------
__device__ __forceinline__ uint32_t smem_to_u32(const void* p) {
    uint32_t a;
    asm("{ .reg .u64 t; cvta.to.shared.u64 t, %1; cvt.u32.u64 %0, t; }" : "=r"(a) : "l"(p));
    return a;
}

#define MBARRIER_INIT(addr, cnt) \
    asm volatile("mbarrier.init.shared.b64 [%0], %1;" :: "r"((uint32_t)(addr)), "r"((uint32_t)(cnt)) : "memory")

#define MBARRIER_ARRIVE(addr) \
    asm volatile("mbarrier.arrive.shared.b64 _, [%0];" :: "r"((uint32_t)(addr)) : "memory")

#define MBARRIER_EXPECT_TX(addr, bytes) \
    asm volatile("mbarrier.arrive.expect_tx.shared.b64 _, [%0], %1;" :: "r"((uint32_t)(addr)), "r"((uint32_t)(bytes)) : "memory")

#define MBARRIER_WAIT_PARITY(addr, parity) do { \
    uint32_t _m = (uint32_t)(addr); uint32_t _p = (uint32_t)(parity); uint32_t _d; \
    asm volatile("{\n\t.reg .pred p;\n\t" \
        "mbarrier.try_wait.parity.acquire.cta.shared::cta.b64 p, [%1], %2;\n\t" \
        "selp.b32 %0, 1, 0, p;\n\t}" : "=r"(_d) : "r"(_m), "r"(_p) : "memory"); \
    if (!_d) { \
        asm volatile("{\n\t.reg .pred P1;\n\t" \
            "WL_%=:\n\t" \
            "mbarrier.try_wait.parity.acquire.cta.shared::cta.b64 P1, [%0], %1, 0x989680;\n\t" \
            "@P1 bra.uni WD_%=;\n\t" \
            "bra.uni WL_%=;\n\t" \
            "WD_%=:\n\t}" :: "r"(_m), "r"(_p) : "memory"); \
    } \
} while (0)

#define FENCE_PROXY_ASYNC() asm volatile("fence.proxy.async.shared::cta;" ::: "memory")

#define CLUSTER_SYNC() do { \
    asm volatile("barrier.cluster.arrive.aligned;" ::: "memory"); \
    asm volatile("barrier.cluster.wait.aligned;" ::: "memory"); \
} while (0)

// -------- tcgen05 (sm_103a-only) --------
#define TCGEN05_ALLOC(smem_addr, ncols) \
    asm volatile("tcgen05.alloc.cta_group::1.sync.aligned.shared::cta.b32 [%0], %1;" \
        :: "r"((uint32_t)(smem_addr)), "r"((uint32_t)(ncols)) : "memory")

#define TCGEN05_DEALLOC(tmem, ncols) \
    asm volatile("tcgen05.dealloc.cta_group::1.sync.aligned.b32 %0, %1;" :: "r"(tmem), "r"((uint32_t)(ncols)))

#define TCGEN05_RELINQUISH() \
    asm volatile("tcgen05.relinquish_alloc_permit.cta_group::1.sync.aligned;")

#define TCGEN05_COMMIT(mbar) \
    asm volatile("tcgen05.commit.cta_group::1.mbarrier::arrive::one.shared::cluster.b64 [%0];" \
        :: "r"((uint32_t)(mbar)) : "memory")

#define TCGEN05_COMMIT_MULTICAST(mbar, mask) \
    asm volatile("tcgen05.commit.cta_group::1.mbarrier::arrive::one.shared::cluster.multicast::cluster.b64 [%0], %1;" \
        :: "r"((uint32_t)(mbar)), "h"((uint16_t)(mask)) : "memory")

#define TCGEN05_FENCE_AFTER()  asm volatile("tcgen05.fence::after_thread_sync;" ::: "memory")
#define TCGEN05_FENCE_BEFORE() asm volatile("tcgen05.fence::before_thread_sync;" ::: "memory")
#define TCGEN05_WAIT_LD()      asm volatile("tcgen05.wait::ld.sync.aligned;" ::: "memory")

#define TCGEN05_LD_32X32B_X32(r, tmem_addr) \
    asm volatile( \
        "tcgen05.ld.sync.aligned.32x32b.x32.b32 " \
        "{%0, %1, %2, %3, %4, %5, %6, %7, " \
        " %8, %9, %10, %11, %12, %13, %14, %15, " \
        " %16, %17, %18, %19, %20, %21, %22, %23, " \
        " %24, %25, %26, %27, %28, %29, %30, %31}, [%32];" \
        : "=r"((r)[0]),  "=r"((r)[1]),  "=r"((r)[2]),  "=r"((r)[3]), \
          "=r"((r)[4]),  "=r"((r)[5]),  "=r"((r)[6]),  "=r"((r)[7]), \
          "=r"((r)[8]),  "=r"((r)[9]),  "=r"((r)[10]), "=r"((r)[11]), \
          "=r"((r)[12]), "=r"((r)[13]), "=r"((r)[14]), "=r"((r)[15]), \
          "=r"((r)[16]), "=r"((r)[17]), "=r"((r)[18]), "=r"((r)[19]), \
          "=r"((r)[20]), "=r"((r)[21]), "=r"((r)[22]), "=r"((r)[23]), \
          "=r"((r)[24]), "=r"((r)[25]), "=r"((r)[26]), "=r"((r)[27]), \
          "=r"((r)[28]), "=r"((r)[29]), "=r"((r)[30]), "=r"((r)[31]) \
        : "r"(tmem_addr))

static constexpr uint64_t SMEM_DESC_BASE_SW128 =
    (uint64_t(2) << 61) | (uint64_t(1) << 46) | (uint64_t(64) << 32) | (uint64_t(1) << 16);
#define MAKE_SMEM_DESC(base_addr) (SMEM_DESC_BASE_SW128 | ((uint64_t)((base_addr) >> 4) & 0x3FFF))

__device__ __forceinline__ void tma_load_2d_mc(uint32_t smem_addr, const void* tmap,
                                               int32_t cx, int32_t cy, uint32_t mbar,
                                               uint16_t mask) {
    asm volatile(
        "cp.async.bulk.tensor.2d.shared::cluster.global.tile.mbarrier::complete_tx::bytes.multicast::cluster "
        "[%0], [%1, {%2, %3}], [%4], %5;"
        :: "r"(smem_addr), "l"(tmap), "r"(cx), "r"(cy), "r"(mbar), "h"(mask) : "memory");
}

#if defined(__CUDA_ARCH__) && defined(__CUDA_ARCH_FEAT_SM103_ALL)
__device__ __forceinline__ void mma_f16_ss(uint32_t d_tmem, uint64_t a_desc, uint64_t b_desc,
                                           uint32_t idesc, bool acc) {
    uint32_t en = acc ? 1u : 0u;
    asm volatile(
        "{\n\t.reg .pred p;\n\tsetp.ne.u32 p, %4, 0;\n\t"
        "tcgen05.mma.cta_group::1.kind::f16 [%0], %1, %2, %3, {%5, %5, %5, %5}, p;\n\t}"
        :: "r"(d_tmem), "l"(a_desc), "l"(b_desc), "r"(idesc), "r"(en), "r"(0u) : "memory");
}
#endif

// ---------------- fused prologue: x fp32->fp16 AND dequant+transpose W^T ----------------
#define CVT_BLOCKS 16384   // 16384 * 256 threads * 4 floats = 16.7M elems
__global__ void __launch_bounds__(256) prep_kernel(const float* __restrict__ x,
                                                   const int* __restrict__ qw,
                                                   const int* __restrict__ qz,
                                                   const float* __restrict__ sc) {
    int bid = blockIdx.x;
    if (bid < CVT_BLOCKS) {
        size_t i = (size_t)bid * 256 + threadIdx.x;   // one float4 each
        float4 v = reinterpret_cast<const float4*>(x)[i];
        __half h[4];
        h[0] = __float2half_rn(v.x);
        h[1] = __float2half_rn(v.y);
        h[2] = __float2half_rn(v.z);
        h[3] = __float2half_rn(v.w);
        *reinterpret_cast<uint2*>(g_A + i * 4) = *reinterpret_cast<uint2*>(h);
    } else {
        int i = (bid - CVT_BLOCKS) * 256 + threadIdx.x;  // 512*4096 total
        int n  = i & (NOUT - 1);
        int kp = i >> 12;                 // packed-k row [0,512)
        int g  = kp >> 4;
        unsigned w  = (unsigned)qw[(size_t)kp * NOUT + n];
        unsigned zw = (unsigned)qz[(size_t)g * (NOUT / 8) + (n >> 3)];
        float z = (float)(((zw >> ((n & 7) * 4)) & 15u) + 1u);
        float s = sc[(size_t)g * NOUT + n];
        __half h[8];
#pragma unroll
        for (int j = 0; j < 8; j++) {
            float wv = (float)((w >> (4 * j)) & 15u);
            h[j] = __float2half_rn(s * (wv - z));
        }
        *reinterpret_cast<uint4*>(g_B + (size_t)n * KSEG + (size_t)kp * 8) =
            *reinterpret_cast<uint4*>(h);
    }
}

// ---------------- persistent GEMM: 33 clusters x 4 CTAs, TMEM double-buffered acc ----------
// warps 0-3: epilogue, warp 4: TMA producer, warp 5: MMA.
// Each 2x2 cluster processes super-tiles st = cid, cid+33, cid+66, cid+99 (< 128).
// Super-tile st: smt = st % 16 (M block of 256 rows), snt = st / 16 (N block of 512 cols).
// CTA (cx,cy): mtile = smt*2 + cy, ntile = snt*2 + cx.
__global__ void __launch_bounds__(192, 1) __cluster_dims__(2, 2, 1) gemm_kernel(
    const __grid_constant__ CUtensorMap tmapA,
    const __grid_constant__ CUtensorMap tmapB,
    const float* __restrict__ bias,
    float* __restrict__ out)
{
#if defined(__CUDA_ARCH__) && defined(__CUDA_ARCH_FEAT_SM103_ALL)
    extern __shared__ __align__(1024) char smem[];
    uint32_t sb = smem_to_u32(smem);
    const int tid = threadIdx.x, wid = tid >> 5, lid = tid & 31;
    const int cx = blockIdx.x, cy = blockIdx.y, cid = blockIdx.z;
    const int ntiles = (cid < NSUPER - 3 * NCLUSTERS ? 4 : 3);   // 29 clusters get 4, 4 get 3
    const uint16_t maskA = (uint16_t)(0x3u << (2 * cy));   // same-cy pair shares A
    const uint16_t maskB = (uint16_t)(0x5u << cx);         // same-cx pair shares B

    const uint32_t tmem_ptr_addr = sb + 0;
    auto full_bar  = [&](int s) { return sb + 64 + s * 8; };
    auto empty_bar = [&](int s) { return sb + 128 + s * 8; };
    auto done_bar  = [&](int b) { return sb + 192 + b * 8; };
    auto epi_free  = [&](int b) { return sb + 208 + b * 8; };
    auto stageA = [&](int s) { return sb + SMEM_TILES_OFF + s * STAGE_BYTES; };
    auto stageB = [&](int s) { return sb + SMEM_TILES_OFF + s * STAGE_BYTES + A_TILE_BYTES; };

    if (tid == 0) {
#pragma unroll
        for (int s = 0; s < STAGES; s++) {
            MBARRIER_INIT(full_bar(s), 1);
            MBARRIER_INIT(empty_bar(s), 4);   // commit-multicast from all 4 cluster CTAs
        }
        MBARRIER_INIT(done_bar(0), 1);
        MBARRIER_INIT(done_bar(1), 1);
        MBARRIER_INIT(epi_free(0), 4);        // 4 epilogue warps' lane0
        MBARRIER_INIT(epi_free(1), 4);
        FENCE_PROXY_ASYNC();
    }
    if (wid == 5) {
        TCGEN05_ALLOC(tmem_ptr_addr, 512);    // two 256-col accumulator buffers
        TCGEN05_RELINQUISH();
    }
    __syncthreads();
    CLUSTER_SYNC();

    uint32_t tmem_base;
    asm volatile("ld.shared.b32 %0, [%1];" : "=r"(tmem_base) : "r"(tmem_ptr_addr));

    if (wid == 4 && lid == 0) {
        // ---- TMA producer: flat loop over (tile, kiter) ----
        int s = 0, eph = 1;
        for (int t = 0; t < ntiles; t++) {
            const int st = cid + t * NCLUSTERS;
            const int mrow = ((st & (M_SUPERS - 1)) * 2 + cy) * TILE_M + cx * 64;
            const int nrow = ((st >> 4) * 2 + cx) * TILE_N + cy * 128;
            for (int it = 0; it < KITERS; it++) {
                MBARRIER_WAIT_PARITY(empty_bar(s), eph);
                MBARRIER_EXPECT_TX(full_bar(s), STAGE_BYTES);
                tma_load_2d_mc(stageA(s) + cx * A_SLICE_BYTES, &tmapA,
                               it * TILE_K, mrow, full_bar(s), maskA);
                tma_load_2d_mc(stageB(s) + cy * B_SLICE_BYTES, &tmapB,
                               it * TILE_K, nrow, full_bar(s), maskB);
                if (++s == STAGES) { s = 0; eph ^= 1; }
            }
        }
    } else if (wid == 5 && lid == 0) {
        // ---- MMA issuer ----
        int s = 0, fph = 0;
        for (int t = 0; t < ntiles; t++) {
            const int b = t & 1, u = t >> 1;
            MBARRIER_WAIT_PARITY(epi_free(b), (u & 1) ^ 1);   // buffer free?
            const uint32_t acc = tmem_base + b * 256;
            for (int it = 0; it < KITERS; it++) {
                MBARRIER_WAIT_PARITY(full_bar(s), fph);
                uint64_t ad = MAKE_SMEM_DESC(stageA(s));
                uint64_t bd = MAKE_SMEM_DESC(stageB(s));
#pragma unroll
                for (int k = 0; k < 4; k++)
                    mma_f16_ss(acc, ad + k * 2, bd + k * 2, MMA_IDESC, !(it == 0 && k == 0));
                TCGEN05_COMMIT_MULTICAST(empty_bar(s), 0xF);
                if (++s == STAGES) { s = 0; fph ^= 1; }
            }
            TCGEN05_COMMIT(done_bar(b));   // local: this CTA's tile accumulator complete
        }
    } else if (wid < 4) {
        // ---- epilogue: overlaps next tile's mainloop via double buffer ----
        for (int t = 0; t < ntiles; t++) {
            const int b = t & 1, u = t >> 1;
            MBARRIER_WAIT_PARITY(done_bar(b), u & 1);
            TCGEN05_FENCE_AFTER();
            const int st = cid + t * NCLUSTERS;
            const int mtile = (st & (M_SUPERS - 1)) * 2 + cy;
            const int ntile = (st >> 4) * 2 + cx;
            const int m = mtile * TILE_M + wid * 32 + lid;
            float* orow = out + (size_t)m * NOUT + ntile * TILE_N;
            const uint32_t acc = tmem_base + b * 256;
#pragma unroll
            for (int cb = 0; cb < TILE_N / 32; cb++) {
                uint32_t r[32];
                TCGEN05_LD_32X32B_X32(r, acc + cb * 32);
                TCGEN05_WAIT_LD();
                const int n0 = ntile * TILE_N + cb * 32;
#pragma unroll
                for (int i = 0; i < 32; i += 4) {
                    float4 b4 = *reinterpret_cast<const float4*>(bias + n0 + i);
                    float4 v;
                    v.x = __uint_as_float(r[i + 0]) + b4.x;
                    v.y = __uint_as_float(r[i + 1]) + b4.y;
                    v.z = __uint_as_float(r[i + 2]) + b4.z;
                    v.w = __uint_as_float(r[i + 3]) + b4.w;
                    *reinterpret_cast<float4*>(orow + cb * 32 + i) = v;
                }
            }
            TCGEN05_FENCE_BEFORE();
            if (lid == 0) MBARRIER_ARRIVE(epi_free(b));   // buffer b reusable
        }
    }

    __syncthreads();
    if (wid == 5) TCGEN05_DEALLOC(tmem_base, 512);
    CLUSTER_SYNC();   // peers may still multicast into this CTA's SMEM
#endif  // __CUDA_ARCH_FEAT_SM103_ALL
}

// ---------------- fallback GEMM (body only when tcgen05 is unavailable) ----------------
#define FB_TM 128
#define FB_TN 128
#define FB_TK 32

__global__ void __launch_bounds__(256) gemm_fallback(const float* __restrict__ bias,
                                                     float* __restrict__ out) {
#if defined(__CUDA_ARCH__) && !defined(__CUDA_ARCH_FEAT_SM103_ALL)
    __shared__ __half sA[FB_TK][FB_TM + 4];
    __shared__ __half sB[FB_TK][FB_TN + 4];
    const int tid = threadIdx.x;
    const int m0 = blockIdx.y * FB_TM, n0 = blockIdx.x * FB_TN;
    const int tm = (tid >> 4) * 8, tn = (tid & 15) * 8;
    float acc[8][8] = {};
    for (int k0 = 0; k0 < KSEG; k0 += FB_TK) {
        __syncthreads();
        for (int idx = tid; idx < FB_TM * FB_TK / 8; idx += 256) {
            int row = idx >> 2;
            int kc  = (idx & 3) * 8;
            __half ta[8], tb[8];
            *reinterpret_cast<uint4*>(ta) =
                *reinterpret_cast<const uint4*>(&g_A[(size_t)(m0 + row) * KSEG + k0 + kc]);
            *reinterpret_cast<uint4*>(tb) =
                *reinterpret_cast<const uint4*>(&g_B[(size_t)(n0 + row) * KSEG + k0 + kc]);
#pragma unroll
            for (int j = 0; j < 8; j++) { sA[kc + j][row] = ta[j]; sB[kc + j][row] = tb[j]; }
        }
        __syncthreads();
#pragma unroll 4
        for (int kk = 0; kk < FB_TK; kk++) {
            float a[8], b[8];
#pragma unroll
            for (int j = 0; j < 8; j++) a[j] = __half2float(sA[kk][tm + j]);
#pragma unroll
            for (int j = 0; j < 8; j++) b[j] = __half2float(sB[kk][tn + j]);
#pragma unroll
            for (int i = 0; i < 8; i++)
#pragma unroll
                for (int j = 0; j < 8; j++) acc[i][j] += a[i] * b[j];
        }
    }
#pragma unroll
    for (int i = 0; i < 8; i++)
#pragma unroll
        for (int j = 0; j < 8; j++)
            out[(size_t)(m0 + tm + i) * NOUT + n0 + tn + j] = acc[i][j] + bias[n0 + tn + j];
#endif
}

// ---------------- host ----------------
typedef CUresult (*PFN_encodeTiled)(CUtensorMap*, CUtensorMapDataType, cuuint32_t, void*,
                                    const cuuint64_t*, const cuuint64_t*, const cuuint32_t*,
                                    const cuuint32_t*, CUtensorMapInterleave, CUtensorMapSwizzle,
                                    CUtensorMapL2promotion, CUtensorMapFloatOOBfill);

static void make_tmap(PFN_encodeTiled enc, CUtensorMap* m, void* ptr,
                      uint64_t rows, uint32_t box_rows) {
    cuuint64_t dims[2]    = {(cuuint64_t)KSEG, (cuuint64_t)rows};
    cuuint64_t strides[1] = {(cuuint64_t)KSEG * 2};
    cuuint32_t box[2]     = {(cuuint32_t)TILE_K, (cuuint32_t)box_rows};
    cuuint32_t es[2]      = {1, 1};
    enc(m, CU_TENSOR_MAP_DATA_TYPE_FLOAT16, 2, ptr, dims, strides, box, es,
        CU_TENSOR_MAP_INTERLEAVE_NONE, CU_TENSOR_MAP_SWIZZLE_128B,
        CU_TENSOR_MAP_L2_PROMOTION_L2_128B, CU_TENSOR_MAP_FLOAT_OOB_FILL_NONE);
}

extern "C" void kernel_launch(void* const* d_in, const int* in_sizes, int n_in,
                              void* d_out, int out_size) {
    const float* x    = (const float*)d_in[0];
    const int*   qw   = (const int*)d_in[1];
    const int*   qz   = (const int*)d_in[2];
    const float* sc   = (const float*)d_in[3];
    const float* bias = (const float*)d_in[4];
    float* out        = (float*)d_out;

    void* pA = nullptr; void* pB = nullptr;
    cudaGetSymbolAddress(&pA, g_A);
    cudaGetSymbolAddress(&pB, g_B);

    void* fn = nullptr;
    cudaDriverEntryPointQueryResult qr;
    cudaGetDriverEntryPointByVersion("cuTensorMapEncodeTiled", &fn, 12000,
                                     cudaEnableDefault, &qr);
    PFN_encodeTiled enc = (PFN_encodeTiled)fn;

    CUtensorMap tA, tB;
    make_tmap(enc, &tA, pA, MROWS, 64);    // A: 64-row cooperative slices
    make_tmap(enc, &tB, pB, NOUT, 128);    // B: 128-row cooperative slices

    cudaFuncSetAttribute(gemm_kernel, cudaFuncAttributeMaxDynamicSharedMemorySize, SMEM_TOTAL);

    // fused prologue
    prep_kernel<<<CVT_BLOCKS + (512 * NOUT) / 256, 256>>>(x, qw, qz, sc);

    // persistent GEMM: 33 clusters of 2x2 (132 CTAs). Exactly one of these two
    // kernels has a body in the loaded cubin; the other is an empty shell.
    gemm_kernel<<<dim3(2, 2, NCLUSTERS), 192, SMEM_TOTAL>>>(tA, tB, bias, out);
    gemm_fallback<<<dim3(NOUT / FB_TN, MROWS / FB_TM), 256>>>(bias, out);
}

// round 5
// speedup vs baseline: 3.0210x; 1.0019x over previous
#include <cuda_runtime.h>
#include <cuda.h>
#include <cuda_bf16.h>
#include <cuda_fp16.h>
#include <cstdint>

// ---------------- problem constants ----------------
#define MROWS 4096
#define NOUT  4096
#define KSEG  4096

// ---------------- GEMM tiling ----------------
#define TILE_M 128
#define TILE_N 256
#define TILE_K 64            // 64 fp16 = 128 bytes = one SW128 row
#define STAGES 4
#define KITERS (KSEG / TILE_K)   // 64

#define NCLUSTERS 33              // 33 clusters x 4 CTAs = 132 CTAs (persistent)
#define NSUPER    128             // (4096/256) * (4096/512) super-tiles
#define M_SUPERS  16              // 4096 / 256

#define A_TILE_BYTES (TILE_M * 128)   // 16384
#define B_TILE_BYTES (TILE_N * 128)   // 32768
#define A_SLICE_BYTES (A_TILE_BYTES / 2)   // 8192  (64 rows)
#define B_SLICE_BYTES (B_TILE_BYTES / 2)   // 16384 (128 rows)
#define STAGE_BYTES  (A_TILE_BYTES + B_TILE_BYTES)
#define SMEM_TILES_OFF 1024
#define SMEM_TOTAL   (SMEM_TILES_OFF + STAGES * STAGE_BYTES)  // 197632

// idesc kind::f16 fp16 inputs: dtype=F32(bit4), N/8 << 17, M/16 << 24
#define MMA_IDESC (0x10u | ((TILE_N / 8) << 17) | ((TILE_M / 16) << 24))

// ---------------- scratch ----------------
__device__ __align__(1024) __half g_A[(size_t)MROWS * KSEG];  // 32 MB
__device__ __align__(1024) __half g_B[(size_t)NOUT * KSEG];   // 32 MB

// ---------------- PTX helpers ----------------
__device__ __forceinline__ uint32_t smem_to_u32(const void* p) {
    uint32_t a;
    asm("{ .reg .u64 t; cvta.to.shared.u64 t, %1; cvt.u32.u64 %0, t; }" : "=r"(a) : "l"(p));
    return a;
}

#define MBARRIER_INIT(addr, cnt) \
    asm volatile("mbarrier.init.shared.b64 [%0], %1;" :: "r"((uint32_t)(addr)), "r"((uint32_t)(cnt)) : "memory")

#define MBARRIER_ARRIVE(addr) \
    asm volatile("mbarrier.arrive.shared.b64 _, [%0];" :: "r"((uint32_t)(addr)) : "memory")

#define MBARRIER_EXPECT_TX(addr, bytes) \
    asm volatile("mbarrier.arrive.expect_tx.shared.b64 _, [%0], %1;" :: "r"((uint32_t)(addr)), "r"((uint32_t)(bytes)) : "memory")

#define MBARRIER_WAIT_PARITY(addr, parity) do { \
    uint32_t _m = (uint32_t)(addr); uint32_t _p = (uint32_t)(parity); uint32_t _d; \
    asm volatile("{\n\t.reg .pred p;\n\t" \
        "mbarrier.try_wait.parity.acquire.cta.shared::cta.b64 p, [%1], %2;\n\t" \
        "selp.b32 %0, 1, 0, p;\n\t}" : "=r"(_d) : "r"(_m), "r"(_p) : "memory"); \
    if (!_d) { \
        asm volatile("{\n\t.reg .pred P1;\n\t" \
            "WL_%=:\n\t" \
            "mbarrier.try_wait.parity.acquire.cta.shared::cta.b64 P1, [%0], %1, 0x989680;\n\t" \
            "@P1 bra.uni WD_%=;\n\t" \
            "bra.uni WL_%=;\n\t" \
            "WD_%=:\n\t}" :: "r"(_m), "r"(_p) : "memory"); \
    } \
} while (0)

#define FENCE_PROXY_ASYNC() asm volatile("fence.proxy.async.shared::cta;" ::: "memory")

#define CLUSTER_SYNC() do { \
    asm volatile("barrier.cluster.arrive.aligned;" ::: "memory"); \
    asm volatile("barrier.cluster.wait.aligned;" ::: "memory"); \
} while (0)

// -------- tcgen05 (sm_103a-only) --------
#define TCGEN05_ALLOC(smem_addr, ncols) \
    asm volatile("tcgen05.alloc.cta_group::1.sync.aligned.shared::cta.b32 [%0], %1;" \
        :: "r"((uint32_t)(smem_addr)), "r"((uint32_t)(ncols)) : "memory")

#define TCGEN05_DEALLOC(tmem, ncols) \
    asm volatile("tcgen05.dealloc.cta_group::1.sync.aligned.b32 %0, %1;" :: "r"(tmem), "r"((uint32_t)(ncols)))

#define TCGEN05_RELINQUISH() \
    asm volatile("tcgen05.relinquish_alloc_permit.cta_group::1.sync.aligned;")

#define TCGEN05_COMMIT(mbar) \
    asm volatile("tcgen05.commit.cta_group::1.mbarrier::arrive::one.shared::cluster.b64 [%0];" \
        :: "r"((uint32_t)(mbar)) : "memory")

#define TCGEN05_COMMIT_MULTICAST(mbar, mask) \
    asm volatile("tcgen05.commit.cta_group::1.mbarrier::arrive::one.shared::cluster.multicast::cluster.b64 [%0], %1;" \
        :: "r"((uint32_t)(mbar)), "h"((uint16_t)(mask)) : "memory")

#define TCGEN05_FENCE_AFTER()  asm volatile("tcgen05.fence::after_thread_sync;" ::: "memory")
#define TCGEN05_FENCE_BEFORE() asm volatile("tcgen05.fence::before_thread_sync;" ::: "memory")
#define TCGEN05_WAIT_LD()      asm volatile("tcgen05.wait::ld.sync.aligned;" ::: "memory")

#define TCGEN05_LD_32X32B_X32(r, tmem_addr) \
    asm volatile( \
        "tcgen05.ld.sync.aligned.32x32b.x32.b32 " \
        "{%0, %1, %2, %3, %4, %5, %6, %7, " \
        " %8, %9, %10, %11, %12, %13, %14, %15, " \
        " %16, %17, %18, %19, %20, %21, %22, %23, " \
        " %24, %25, %26, %27, %28, %29, %30, %31}, [%32];" \
        : "=r"((r)[0]),  "=r"((r)[1]),  "=r"((r)[2]),  "=r"((r)[3]), \
          "=r"((r)[4]),  "=r"((r)[5]),  "=r"((r)[6]),  "=r"((r)[7]), \
          "=r"((r)[8]),  "=r"((r)[9]),  "=r"((r)[10]), "=r"((r)[11]), \
          "=r"((r)[12]), "=r"((r)[13]), "=r"((r)[14]), "=r"((r)[15]), \
          "=r"((r)[16]), "=r"((r)[17]), "=r"((r)[18]), "=r"((r)[19]), \
          "=r"((r)[20]), "=r"((r)[21]), "=r"((r)[22]), "=r"((r)[23]), \
          "=r"((r)[24]), "=r"((r)[25]), "=r"((r)[26]), "=r"((r)[27]), \
          "=r"((r)[28]), "=r"((r)[29]), "=r"((r)[30]), "=r"((r)[31]) \
        : "r"(tmem_addr))

static constexpr uint64_t SMEM_DESC_BASE_SW128 =
    (uint64_t(2) << 61) | (uint64_t(1) << 46) | (uint64_t(64) << 32) | (uint64_t(1) << 16);
#define MAKE_SMEM_DESC(base_addr) (SMEM_DESC_BASE_SW128 | ((uint64_t)((base_addr) >> 4) & 0x3FFF))

__device__ __forceinline__ void tma_load_2d_mc(uint32_t smem_addr, const void* tmap,
                                               int32_t cx, int32_t cy, uint32_t mbar,
                                               uint16_t mask) {
    asm volatile(
        "cp.async.bulk.tensor.2d.shared::cluster.global.tile.mbarrier::complete_tx::bytes.multicast::cluster "
        "[%0], [%1, {%2, %3}], [%4], %5;"
        :: "r"(smem_addr), "l"(tmap), "r"(cx), "r"(cy), "r"(mbar), "h"(mask) : "memory");
}

#if defined(__CUDA_ARCH__) && defined(__CUDA_ARCH_FEAT_SM103_ALL)
__device__ __forceinline__ void mma_f16_ss(uint32_t d_tmem, uint64_t a_desc, uint64_t b_desc,
                                           uint32_t idesc, bool acc) {
    uint32_t en = acc ? 1u : 0u;
    asm volatile(
        "{\n\t.reg .pred p;\n\tsetp.ne.u32 p, %4, 0;\n\t"
        "tcgen05.mma.cta_group::1.kind::f16 [%0], %1, %2, %3, {%5, %5, %5, %5}, p;\n\t}"
        :: "r"(d_tmem), "l"(a_desc), "l"(b_desc), "r"(idesc), "r"(en), "r"(0u) : "memory");
}
#endif

// ---------------- prologue A: x fp32 -> fp16 (coalesced both sides) ----------------
__global__ void __launch_bounds__(256) cvt_x_kernel(const float* __restrict__ x) {
    size_t i = (size_t)blockIdx.x * blockDim.x + threadIdx.x;   // one float4 each
    float4 v = reinterpret_cast<const float4*>(x)[i];
    __half h[4];
    h[0] = __float2half_rn(v.x);
    h[1] = __float2half_rn(v.y);
    h[2] = __float2half_rn(v.z);
    h[3] = __float2half_rn(v.w);
    *reinterpret_cast<uint2*>(g_A + i * 4) = *reinterpret_cast<uint2*>(h);
}

// ---------------- prologue B: dequant + SMEM-transposed coalesced store ----------------
// Block = 64 kp (512 k) x 64 n tile. SMEM: 64x64 16B cells, XOR-swizzled
// cell(kp,n) -> [kp][n ^ kp]. Phase1 (produce) and Phase2 (write-out) are both
// conflict-free per 8-lane phase. Output writes: 512B contiguous per warp.
__global__ void __launch_bounds__(256) dequant_t_kernel(const int* __restrict__ qw,
                                                        const int* __restrict__ qz,
                                                        const float* __restrict__ sc) {
    extern __shared__ uint4 cells[];   // [64][64] = 64 KB
    const int t = threadIdx.x;
    const int n0  = blockIdx.x * 64;
    const int kp0 = blockIdx.y * 64;

    // Phase 1: each thread produces 16 cells
#pragma unroll
    for (int i = 0; i < 16; i++) {
        int idx  = t + 256 * i;
        int kp_l = idx >> 6;
        int n_l  = idx & 63;
        int kp   = kp0 + kp_l;
        int n    = n0 + n_l;
        int g    = kp >> 4;
        unsigned w  = (unsigned)qw[(size_t)kp * NOUT + n];
        unsigned zw = (unsigned)qz[(size_t)g * (NOUT / 8) + (n >> 3)];
        float z = (float)(((zw >> ((n & 7) * 4)) & 15u) + 1u);
        float s = sc[(size_t)g * NOUT + n];
        __half h[8];
#pragma unroll
        for (int j = 0; j < 8; j++) {
            float wv = (float)((w >> (4 * j)) & 15u);
            h[j] = __float2half_rn(s * (wv - z));
        }
        cells[kp_l * 64 + (n_l ^ kp_l)] = *reinterpret_cast<uint4*>(h);
    }
    __syncthreads();

    // Phase 2: write out 64 rows x 1KB, coalesced
#pragma unroll
    for (int i = 0; i < 16; i++) {
        int n_l = i * 4 + (t >> 6);
        int c   = t & 63;                       // = kp_l chunk within row
        uint4 v = cells[c * 64 + (n_l ^ c)];
        // g_B element offset: (n0+n_l)*KSEG + (kp0+c)*8, in uint4 (8 halves) units:
        reinterpret_cast<uint4*>(g_B)[(size_t)(n0 + n_l) * (KSEG / 8) + kp0 + c] = v;
    }
}

// ---------------- persistent GEMM: 33 clusters x 4 CTAs, TMEM double-buffered acc ----------
// warps 0-3: epilogue, warp 4: TMA producer, warp 5: MMA.
__global__ void __launch_bounds__(192, 1) __cluster_dims__(2, 2, 1) gemm_kernel(
    const __grid_constant__ CUtensorMap tmapA,
    const __grid_constant__ CUtensorMap tmapB,
    const float* __restrict__ bias,
    float* __restrict__ out)
{
#if defined(__CUDA_ARCH__) && defined(__CUDA_ARCH_FEAT_SM103_ALL)
    extern __shared__ __align__(1024) char smem[];
    uint32_t sb = smem_to_u32(smem);
    const int tid = threadIdx.x, wid = tid >> 5, lid = tid & 31;
    const int cx = blockIdx.x, cy = blockIdx.y, cid = blockIdx.z;
    const int rank = cy * 2 + cx;
    const int ntiles = (cid < NSUPER - 3 * NCLUSTERS ? 4 : 3);
    const uint16_t maskA = (uint16_t)(0x3u << (2 * cy));   // same-cy pair shares A
    const uint16_t maskB = (uint16_t)(0x5u << cx);         // same-cx pair shares B
    // MMA empty-commit targets: the CTAs whose producers write into THIS CTA's smem
    // = self, x-partner (A slices), y-partner (B slices). Diagonal excluded.
    const uint16_t maskE = (uint16_t)((1u << rank) | (1u << (rank ^ 1)) | (1u << (rank ^ 2)));

    const uint32_t tmem_ptr_addr = sb + 0;
    auto full_bar  = [&](int s) { return sb + 64 + s * 8; };
    auto empty_bar = [&](int s) { return sb + 128 + s * 8; };
    auto done_bar  = [&](int b) { return sb + 192 + b * 8; };
    auto epi_free  = [&](int b) { return sb + 208 + b * 8; };
    auto stageA = [&](int s) { return sb + SMEM_TILES_OFF + s * STAGE_BYTES; };
    auto stageB = [&](int s) { return sb + SMEM_TILES_OFF + s * STAGE_BYTES + A_TILE_BYTES; };

    if (tid == 0) {
#pragma unroll
        for (int s = 0; s < STAGES; s++) {
            MBARRIER_INIT(full_bar(s), 1);
            MBARRIER_INIT(empty_bar(s), 3);   // arrivals: self-MMA, x-partner-MMA, y-partner-MMA
        }
        MBARRIER_INIT(done_bar(0), 1);
        MBARRIER_INIT(done_bar(1), 1);
        MBARRIER_INIT(epi_free(0), 4);        // 4 epilogue warps' lane0
        MBARRIER_INIT(epi_free(1), 4);
        FENCE_PROXY_ASYNC();
    }
    if (wid == 5) {
        TCGEN05_ALLOC(tmem_ptr_addr, 512);    // two 256-col accumulator buffers
        TCGEN05_RELINQUISH();
    }
    __syncthreads();
    CLUSTER_SYNC();

    uint32_t tmem_base;
    asm volatile("ld.shared.b32 %0, [%1];" : "=r"(tmem_base) : "r"(tmem_ptr_addr));

    if (wid == 4 && lid == 0) {
        // ---- TMA producer ----
        int s = 0, eph = 1;
        for (int t = 0; t < ntiles; t++) {
            const int st = cid + t * NCLUSTERS;
            const int mrow = ((st & (M_SUPERS - 1)) * 2 + cy) * TILE_M + cx * 64;
            const int nrow = ((st >> 4) * 2 + cx) * TILE_N + cy * 128;
            for (int it = 0; it < KITERS; it++) {
                MBARRIER_WAIT_PARITY(empty_bar(s), eph);
                MBARRIER_EXPECT_TX(full_bar(s), STAGE_BYTES);
                tma_load_2d_mc(stageA(s) + cx * A_SLICE_BYTES, &tmapA,
                               it * TILE_K, mrow, full_bar(s), maskA);
                tma_load_2d_mc(stageB(s) + cy * B_SLICE_BYTES, &tmapB,
                               it * TILE_K, nrow, full_bar(s), maskB);
                if (++s == STAGES) { s = 0; eph ^= 1; }
            }
        }
    } else if (wid == 5 && lid == 0) {
        // ---- MMA issuer ----
        int s = 0, fph = 0;
        for (int t = 0; t < ntiles; t++) {
            const int b = t & 1, u = t >> 1;
            MBARRIER_WAIT_PARITY(epi_free(b), (u & 1) ^ 1);   // buffer free?
            const uint32_t acc = tmem_base + b * 256;
            for (int it = 0; it < KITERS; it++) {
                MBARRIER_WAIT_PARITY(full_bar(s), fph);
                uint64_t ad = MAKE_SMEM_DESC(stageA(s));
                uint64_t bd = MAKE_SMEM_DESC(stageB(s));
#pragma unroll
                for (int k = 0; k < 4; k++)
                    mma_f16_ss(acc, ad + k * 2, bd + k * 2, MMA_IDESC, !(it == 0 && k == 0));
                TCGEN05_COMMIT_MULTICAST(empty_bar(s), maskE);
                if (++s == STAGES) { s = 0; fph ^= 1; }
            }
            TCGEN05_COMMIT(done_bar(b));
        }
    } else if (wid < 4) {
        // ---- epilogue: overlaps next tile's mainloop via double buffer ----
        for (int t = 0; t < ntiles; t++) {
            const int b = t & 1, u = t >> 1;
            MBARRIER_WAIT_PARITY(done_bar(b), u & 1);
            TCGEN05_FENCE_AFTER();
            const int st = cid + t * NCLUSTERS;
            const int mtile = (st & (M_SUPERS - 1)) * 2 + cy;
            const int ntile = (st >> 4) * 2 + cx;
            const int m = mtile * TILE_M + wid * 32 + lid;
            float* orow = out + (size_t)m * NOUT + ntile * TILE_N;
            const uint32_t acc = tmem_base + b * 256;
#pragma unroll
            for (int cb = 0; cb < TILE_N / 32; cb++) {
                uint32_t r[32];
                TCGEN05_LD_32X32B_X32(r, acc + cb * 32);
                TCGEN05_WAIT_LD();
                const int n0 = ntile * TILE_N + cb * 32;
#pragma unroll
                for (int i = 0; i < 32; i += 4) {
                    float4 b4 = *reinterpret_cast<const float4*>(bias + n0 + i);
                    float4 v;
                    v.x = __uint_as_float(r[i + 0]) + b4.x;
                    v.y = __uint_as_float(r[i + 1]) + b4.y;
                    v.z = __uint_as_float(r[i + 2]) + b4.z;
                    v.w = __uint_as_float(r[i + 3]) + b4.w;
                    *reinterpret_cast<float4*>(orow + cb * 32 + i) = v;
                }
            }
            TCGEN05_FENCE_BEFORE();
            if (lid == 0) MBARRIER_ARRIVE(epi_free(b));
        }
    }

    __syncthreads();
    if (wid == 5) TCGEN05_DEALLOC(tmem_base, 512);
    CLUSTER_SYNC();
#endif  // __CUDA_ARCH_FEAT_SM103_ALL
}

// ---------------- fallback GEMM (body only when tcgen05 is unavailable) ----------------
#define FB_TM 128
#define FB_TN 128
#define FB_TK 32

__global__ void __launch_bounds__(256) gemm_fallback(const float* __restrict__ bias,
                                                     float* __restrict__ out) {
#if defined(__CUDA_ARCH__) && !defined(__CUDA_ARCH_FEAT_SM103_ALL)
    __shared__ __half sA[FB_TK][FB_TM + 4];
    __shared__ __half sB[FB_TK][FB_TN + 4];
    const int tid = threadIdx.x;
    const int m0 = blockIdx.y * FB_TM, n0 = blockIdx.x * FB_TN;
    const int tm = (tid >> 4) * 8, tn = (tid & 15) * 8;
    float acc[8][8] = {};
    for (int k0 = 0; k0 < KSEG; k0 += FB_TK) {
        __syncthreads();
        for (int idx = tid; idx < FB_TM * FB_TK / 8; idx += 256) {
            int row = idx >> 2;
            int kc  = (idx & 3) * 8;
            __half ta[8], tb[8];
            *reinterpret_cast<uint4*>(ta) =
                *reinterpret_cast<const uint4*>(&g_A[(size_t)(m0 + row) * KSEG + k0 + kc]);
            *reinterpret_cast<uint4*>(tb) =
                *reinterpret_cast<const uint4*>(&g_B[(size_t)(n0 + row) * KSEG + k0 + kc]);
#pragma unroll
            for (int j = 0; j < 8; j++) { sA[kc + j][row] = ta[j]; sB[kc + j][row] = tb[j]; }
        }
        __syncthreads();
#pragma unroll 4
        for (int kk = 0; kk < FB_TK; kk++) {
            float a[8], b[8];
#pragma unroll
            for (int j = 0; j < 8; j++) a[j] = __half2float(sA[kk][tm + j]);
#pragma unroll
            for (int j = 0; j < 8; j++) b[j] = __half2float(sB[kk][tn + j]);
#pragma unroll
            for (int i = 0; i < 8; i++)
#pragma unroll
                for (int j = 0; j < 8; j++) acc[i][j] += a[i] * b[j];
        }
    }
#pragma unroll
    for (int i = 0; i < 8; i++)
#pragma unroll
        for (int j = 0; j < 8; j++)
            out[(size_t)(m0 + tm + i) * NOUT + n0 + tn + j] = acc[i][j] + bias[n0 + tn + j];
#endif
}

// ---------------- host ----------------
typedef CUresult (*PFN_encodeTiled)(CUtensorMap*, CUtensorMapDataType, cuuint32_t, void*,
                                    const cuuint64_t*, const cuuint64_t*, const cuuint32_t*,
                                    const cuuint32_t*, CUtensorMapInterleave, CUtensorMapSwizzle,
                                    CUtensorMapL2promotion, CUtensorMapFloatOOBfill);

static void make_tmap(PFN_encodeTiled enc, CUtensorMap* m, void* ptr,
                      uint64_t rows, uint32_t box_rows) {
    cuuint64_t dims[2]    = {(cuuint64_t)KSEG, (cuuint64_t)rows};
    cuuint64_t strides[1] = {(cuuint64_t)KSEG * 2};
    cuuint32_t box[2]     = {(cuuint32_t)TILE_K, (cuuint32_t)box_rows};
    cuuint32_t es[2]      = {1, 1};
    enc(m, CU_TENSOR_MAP_DATA_TYPE_FLOAT16, 2, ptr, dims, strides, box, es,
        CU_TENSOR_MAP_INTERLEAVE_NONE, CU_TENSOR_MAP_SWIZZLE_128B,
        CU_TENSOR_MAP_L2_PROMOTION_L2_128B, CU_TENSOR_MAP_FLOAT_OOB_FILL_NONE);
}

extern "C" void kernel_launch(void* const* d_in, const int* in_sizes, int n_in,
                              void* d_out, int out_size) {
    const float* x    = (const float*)d_in[0];
    const int*   qw   = (const int*)d_in[1];
    const int*   qz   = (const int*)d_in[2];
    const float* sc   = (const float*)d_in[3];
    const float* bias = (const float*)d_in[4];
    float* out        = (float*)d_out;

    void* pA = nullptr; void* pB = nullptr;
    cudaGetSymbolAddress(&pA, g_A);
    cudaGetSymbolAddress(&pB, g_B);

    void* fn = nullptr;
    cudaDriverEntryPointQueryResult qr;
    cudaGetDriverEntryPointByVersion("cuTensorMapEncodeTiled", &fn, 12000,
                                     cudaEnableDefault, &qr);
    PFN_encodeTiled enc = (PFN_encodeTiled)fn;

    CUtensorMap tA, tB;
    make_tmap(enc, &tA, pA, MROWS, 64);    // A: 64-row cooperative slices
    make_tmap(enc, &tB, pB, NOUT, 128);    // B: 128-row cooperative slices

    cudaFuncSetAttribute(gemm_kernel, cudaFuncAttributeMaxDynamicSharedMemorySize, SMEM_TOTAL);
    cudaFuncSetAttribute(dequant_t_kernel, cudaFuncAttributeMaxDynamicSharedMemorySize, 65536);

    // prologues (order irrelevant; both complete before GEMM on the stream)
    dequant_t_kernel<<<dim3(NOUT / 64, 512 / 64), 256, 65536>>>(qw, qz, sc);
    cvt_x_kernel<<<(MROWS * KSEG / 4) / 256, 256>>>(x);

    // persistent GEMM: 33 clusters of 2x2 (132 CTAs). Exactly one of these two
    // kernels has a body in the loaded cubin; the other is an empty shell.
    gemm_kernel<<<dim3(2, 2, NCLUSTERS), 192, SMEM_TOTAL>>>(tA, tB, bias, out);
    gemm_fallback<<<dim3(NOUT / FB_TN, MROWS / FB_TM), 256>>>(bias, out);
}